// round 7
// baseline (speedup 1.0000x reference)
#include <cuda_runtime.h>
#include <stdint.h>

#define N_GRAPHS 1000
#define EPS 1e-5f
#define MAIN_THREADS 1024
#define MAIN_GRID 104   // pipelined: ~1MB live L2 window per block -> 104MB < 126MB L2

__device__ int g_start[N_GRAPHS + 1];
__device__ unsigned int g_ticket;   // dynamic graph scheduler

// ---------------------------------------------------------------------------
// Kernel 1: segment boundaries (int4 vectorized) + ticket reset.
// ---------------------------------------------------------------------------
__global__ void find_starts_kernel(const int* __restrict__ batch, int n) {
    int i4 = blockIdx.x * blockDim.x + threadIdx.x;
    if (i4 == 0) g_ticket = 0;                 // reset scheduler every launch
    int base = i4 * 4;
    if (base >= n) return;

    int v[4];
    if (base + 3 < n) {
        int4 t = ((const int4*)batch)[i4];
        v[0] = t.x; v[1] = t.y; v[2] = t.z; v[3] = t.w;
    } else {
        for (int j = 0; j < 4; ++j) v[j] = (base + j < n) ? batch[base + j] : v[j > 0 ? j - 1 : 0];
    }
    int pb = (base == 0) ? -1 : min(max(batch[base - 1], 0), N_GRAPHS - 1);
    for (int j = 0; j < 4; ++j) {
        int idx = base + j;
        if (idx >= n) break;
        int b = min(max(v[j], 0), N_GRAPHS - 1);
        for (int g = pb + 1; g <= b; ++g) g_start[g] = idx;
        if (idx == n - 1) {
            for (int g = b + 1; g <= N_GRAPHS; ++g) g_start[g] = n;
        }
        pb = b;
    }
}

// ---------------------------------------------------------------------------
// Kernel 2: software-pipelined fused GraphNorm with dynamic tickets.
// Each block overlaps pass2(cur graph: L2 read + DRAM write) with
// pass1(next graph: DRAM read), producing a steady mixed read/write DRAM
// stream chip-wide. Grid capped at 104 so the ~1MB live window per block
// stays L2-resident.
//   lane = tid&31 -> channel quad [4*lane,4*lane+4); grp = tid>>5 -> row group
//   One-pass variance: var = E_w[x^2] + mean^2 * ms * (ms - 2)
//   out = A[c]*x + B[c],  A = weight*rsqrt(var+eps), B = bias - mean*ms*A
// ---------------------------------------------------------------------------
__global__ __launch_bounds__(MAIN_THREADS, 1)
void graphnorm_kernel(const float4* __restrict__ x,
                      const float* __restrict__ nw,
                      const float* __restrict__ weight,
                      const float* __restrict__ bias,
                      const float* __restrict__ msc,
                      float4* __restrict__ out) {
    // partials: [group][channel], row stride 132 floats (528B) to dodge conflicts
    __shared__ float s_sum [32][132];
    __shared__ float s_sum2[32][132];
    __shared__ float s_wp[32];
    __shared__ float s_A[128];
    __shared__ float s_B[128];
    __shared__ int   s_g;

    const int tid  = threadIdx.x;
    const int lane = tid & 31;
    const int grp  = tid >> 5;

    int  curg = -1, cur_s = 0, cur_len = 0;
    float4 A = make_float4(0.f, 0.f, 0.f, 0.f);
    float4 B = make_float4(0.f, 0.f, 0.f, 0.f);

    while (true) {
        if (tid == 0) s_g = (int)atomicAdd(&g_ticket, 1u);
        __syncthreads();
        const int nextg = s_g;
        const bool hasN = (nextg < N_GRAPHS);
        const bool hasC = (curg >= 0);
        if (!hasN && !hasC) break;

        int sN = 0, lenN = 0;
        if (hasN) { sN = g_start[nextg]; lenN = g_start[nextg + 1] - sN; }
        const int iters = max(lenN, cur_len);

        float4 wx  = make_float4(0.f, 0.f, 0.f, 0.f);
        float4 wx2 = make_float4(0.f, 0.f, 0.f, 0.f);
        float  wa  = 0.f;

        // ---- combined loop: pass1(next, DRAM read) + pass2(cur, L2 read + write)
        #pragma unroll 4
        for (int r = grp; r < iters; r += 32) {
            if (r < lenN) {
                const int row = sN + r;
                float  w = __ldg(&nw[row]);
                float4 v = __ldg(&x[(size_t)row * 32 + lane]);   // keep in L2
                wa += w;
                wx.x += w * v.x;  wx.y += w * v.y;
                wx.z += w * v.z;  wx.w += w * v.w;
                wx2.x += w * v.x * v.x;  wx2.y += w * v.y * v.y;
                wx2.z += w * v.z * v.z;  wx2.w += w * v.w * v.w;
            }
            if (r < cur_len) {
                const int row = cur_s + r;
                float4 v = __ldcs(&x[(size_t)row * 32 + lane]);  // last use
                float4 o;
                o.x = fmaf(A.x, v.x, B.x);
                o.y = fmaf(A.y, v.y, B.y);
                o.z = fmaf(A.z, v.z, B.z);
                o.w = fmaf(A.w, v.w, B.w);
                __stcs(&out[(size_t)row * 32 + lane], o);        // streaming store
            }
        }

        if (!hasN) break;                          // flushed the final graph

        // ---- single-stage reduction + coefficients for `next` ----
        *(float4*)&s_sum [grp][4 * lane] = wx;
        *(float4*)&s_sum2[grp][4 * lane] = wx2;
        if (lane == 0) s_wp[grp] = wa;
        __syncthreads();

        if (tid < 128) {                           // thread t owns channel t
            float swx = 0.f, swx2 = 0.f, sw = 0.f;
            #pragma unroll
            for (int g2 = 0; g2 < 32; ++g2) {
                swx  += s_sum [g2][tid];
                swx2 += s_sum2[g2][tid];
                sw   += s_wp[g2];
            }
            float inv_w = 1.0f / fmaxf(sw, 1e-12f);
            float m  = swx  * inv_w;
            float m2 = swx2 * inv_w;
            float ms = __ldg(&msc[tid]);
            float wt = __ldg(&weight[tid]);
            float bs = __ldg(&bias[tid]);
            float var = m2 + m * m * ms * (ms - 2.f);
            float a = wt * rsqrtf(var + EPS);
            s_A[tid] = a;
            s_B[tid] = bs - m * ms * a;
        }
        __syncthreads();

        A = *(const float4*)&s_A[4 * lane];
        B = *(const float4*)&s_B[4 * lane];

        curg = nextg; cur_s = sN; cur_len = lenN;
    }
}

// ---------------------------------------------------------------------------
// Launch
// ---------------------------------------------------------------------------
extern "C" void kernel_launch(void* const* d_in, const int* in_sizes, int n_in,
                              void* d_out, int out_size) {
    const float* x      = (const float*)d_in[0];
    const int*   batch  = (const int*)d_in[1];     // int32 (JAX x64 disabled)
    const float* nw     = (const float*)d_in[2];
    const float* weight = (const float*)d_in[3];
    const float* bias   = (const float*)d_in[4];
    const float* msc    = (const float*)d_in[5];
    float* out = (float*)d_out;

    const int n = in_sizes[1];

    const int n4 = (n + 3) / 4;
    find_starts_kernel<<<(n4 + 255) / 256, 256>>>(batch, n);
    graphnorm_kernel<<<MAIN_GRID, MAIN_THREADS>>>(
        (const float4*)x, nw, weight, bias, msc, (float4*)out);
}

// round 9
// speedup vs baseline: 1.7331x; 1.7331x over previous
#include <cuda_runtime.h>
#include <stdint.h>

#define N_GRAPHS 1000
#define EPS 1e-5f
#define MAIN_THREADS 1024
#define MAIN_GRID 152   // 152 SMs; live L2 window 152*512KB=78MB < 126MB L2

__device__ int g_start[N_GRAPHS + 1];
__device__ unsigned int g_ticket;   // dynamic graph scheduler

// ---- L2 residency-hinted 128-bit loads via cache-policy descriptor --------
__device__ __forceinline__ unsigned long long mkpol_evict_last() {
    unsigned long long p;
    asm("createpolicy.fractional.L2::evict_last.b64 %0, 1.0;" : "=l"(p));
    return p;
}
__device__ __forceinline__ unsigned long long mkpol_evict_first() {
    unsigned long long p;
    asm("createpolicy.fractional.L2::evict_first.b64 %0, 1.0;" : "=l"(p));
    return p;
}
__device__ __forceinline__ float4 ldg_pol(const float4* p, unsigned long long pol) {
    float4 v;
    asm("ld.global.nc.L2::cache_hint.v4.f32 {%0,%1,%2,%3}, [%4], %5;"
        : "=f"(v.x), "=f"(v.y), "=f"(v.z), "=f"(v.w) : "l"(p), "l"(pol));
    return v;
}

// ---------------------------------------------------------------------------
// Kernel 1: segment boundaries (int4 vectorized) + ticket reset.
// ---------------------------------------------------------------------------
__global__ void find_starts_kernel(const int* __restrict__ batch, int n) {
    int i4 = blockIdx.x * blockDim.x + threadIdx.x;
    if (i4 == 0) g_ticket = 0;                 // reset scheduler every launch
    int base = i4 * 4;
    if (base >= n) return;

    int v[4];
    if (base + 3 < n) {
        int4 t = ((const int4*)batch)[i4];
        v[0] = t.x; v[1] = t.y; v[2] = t.z; v[3] = t.w;
    } else {
        for (int j = 0; j < 4; ++j) v[j] = (base + j < n) ? batch[base + j] : v[j > 0 ? j - 1 : 0];
    }
    int pb = (base == 0) ? -1 : min(max(batch[base - 1], 0), N_GRAPHS - 1);
    for (int j = 0; j < 4; ++j) {
        int idx = base + j;
        if (idx >= n) break;
        int b = min(max(v[j], 0), N_GRAPHS - 1);
        for (int g = pb + 1; g <= b; ++g) g_start[g] = idx;
        if (idx == n - 1) {
            for (int g = b + 1; g <= N_GRAPHS; ++g) g_start[g] = n;
        }
        pb = b;
    }
}

// ---------------------------------------------------------------------------
// Kernel 2: fused GraphNorm, sequential per graph (pass1 -> reduce -> pass2),
// dynamic tickets, L2 policy hints: pass-1 x loads pinned (evict_last) for the
// pass-2 re-read; pass-2 x loads demoted (evict_first).
//   lane = tid&31 -> channel quad [4*lane,4*lane+4); grp = tid>>5 -> row group
//   One-pass variance: var = E_w[x^2] + mean^2 * ms * (ms - 2)
//   out = A[c]*x + B[c],  A = weight*rsqrt(var+eps), B = bias - mean*ms*A
// ---------------------------------------------------------------------------
__global__ __launch_bounds__(MAIN_THREADS, 1)
void graphnorm_kernel(const float4* __restrict__ x,
                      const float* __restrict__ nw,
                      const float* __restrict__ weight,
                      const float* __restrict__ bias,
                      const float* __restrict__ msc,
                      float4* __restrict__ out) {
    // partials: [group][channel], row stride 132 floats (528B) to dodge conflicts
    __shared__ float s_sum [32][132];
    __shared__ float s_sum2[32][132];
    __shared__ float s_wp[32];
    __shared__ float s_A[128];
    __shared__ float s_B[128];
    __shared__ int   s_g;

    const int tid  = threadIdx.x;
    const int lane = tid & 31;
    const int grp  = tid >> 5;

    const unsigned long long pol_last  = mkpol_evict_last();
    const unsigned long long pol_first = mkpol_evict_first();

    while (true) {
        if (tid == 0) s_g = (int)atomicAdd(&g_ticket, 1u);
        __syncthreads();
        const int g = s_g;
        if (g >= N_GRAPHS) break;

        const int start = g_start[g];
        const int end   = g_start[g + 1];

        // ---- Pass 1: weighted sums (DRAM read; pin lines in L2) ----
        float4 wx  = make_float4(0.f, 0.f, 0.f, 0.f);
        float4 wx2 = make_float4(0.f, 0.f, 0.f, 0.f);
        float  wa  = 0.f;
        #pragma unroll 4
        for (int r = start + grp; r < end; r += 32) {
            float  w = __ldg(&nw[r]);
            float4 v = ldg_pol(&x[(size_t)r * 32 + lane], pol_last);  // pin for reuse
            wa += w;
            wx.x += w * v.x;  wx.y += w * v.y;
            wx.z += w * v.z;  wx.w += w * v.w;
            wx2.x += w * v.x * v.x;  wx2.y += w * v.y * v.y;
            wx2.z += w * v.z * v.z;  wx2.w += w * v.w * v.w;
        }
        *(float4*)&s_sum [grp][4 * lane] = wx;
        *(float4*)&s_sum2[grp][4 * lane] = wx2;
        if (lane == 0) s_wp[grp] = wa;
        __syncthreads();

        // ---- Single-stage reduction + coefficients (threads 0..127) ----
        if (tid < 128) {                          // thread t owns channel t
            float swx = 0.f, swx2 = 0.f, sw = 0.f;
            #pragma unroll
            for (int g2 = 0; g2 < 32; ++g2) {
                swx  += s_sum [g2][tid];
                swx2 += s_sum2[g2][tid];
                sw   += s_wp[g2];
            }
            float inv_w = 1.0f / fmaxf(sw, 1e-12f);
            float m  = swx  * inv_w;
            float m2 = swx2 * inv_w;
            float ms = __ldg(&msc[tid]);
            float wt = __ldg(&weight[tid]);
            float bs = __ldg(&bias[tid]);
            float var = m2 + m * m * ms * (ms - 2.f);
            float a = wt * rsqrtf(var + EPS);
            s_A[tid] = a;
            s_B[tid] = bs - m * ms * a;
        }
        __syncthreads();

        const float4 A = *(const float4*)&s_A[4 * lane];
        const float4 B = *(const float4*)&s_B[4 * lane];

        // ---- Pass 2: normalize + write (L2 hits; release lines) ----
        #pragma unroll 4
        for (int r = start + grp; r < end; r += 32) {
            float4 v = ldg_pol(&x[(size_t)r * 32 + lane], pol_first); // last use
            float4 o;
            o.x = fmaf(A.x, v.x, B.x);
            o.y = fmaf(A.y, v.y, B.y);
            o.z = fmaf(A.z, v.z, B.z);
            o.w = fmaf(A.w, v.w, B.w);
            __stcs(&out[(size_t)r * 32 + lane], o);         // streaming store
        }
        __syncthreads();   // smem/s_g reuse safety for next iteration
    }
}

// ---------------------------------------------------------------------------
// Launch
// ---------------------------------------------------------------------------
extern "C" void kernel_launch(void* const* d_in, const int* in_sizes, int n_in,
                              void* d_out, int out_size) {
    const float* x      = (const float*)d_in[0];
    const int*   batch  = (const int*)d_in[1];     // int32 (JAX x64 disabled)
    const float* nw     = (const float*)d_in[2];
    const float* weight = (const float*)d_in[3];
    const float* bias   = (const float*)d_in[4];
    const float* msc    = (const float*)d_in[5];
    float* out = (float*)d_out;

    const int n = in_sizes[1];

    const int n4 = (n + 3) / 4;
    find_starts_kernel<<<(n4 + 255) / 256, 256>>>(batch, n);
    graphnorm_kernel<<<MAIN_GRID, MAIN_THREADS>>>(
        (const float4*)x, nw, weight, bias, msc, (float4*)out);
}